// round 1
// baseline (speedup 1.0000x reference)
#include <cuda_runtime.h>
#include <cuda_bf16.h>
#include <math.h>

// Problem dims (fixed by the dataset)
#define NN 8192
#define DD 1024
#define HH 4096
#define KK 4096   // codebook

// ---------------- scratch (static __device__, allocation-free) ----------------
__device__ float g_hcat[(size_t)NN * 2 * HH];   // [8192, 8192] = 256 MB
__device__ float g_h2[(size_t)NN * HH];         // [8192, 4096] = 128 MB (reused for scores)
__device__ float g_h3[(size_t)NN * HH];         // [8192, 4096] = 128 MB
__device__ float g_z[(size_t)NN * DD];          // [8192, 1024] =  32 MB
__device__ float g_e2[KK];
__device__ int   g_idx[NN];

// ---------------- GEMM: C[m,n] = act( sum_k A[m,k]*B[n,k] + bias[n] ) --------
// A: [M,K] row-major, B: [N,K] row-major. All dims multiples of tile sizes.
#define BM 128
#define BN 128
#define BK 8
#define TM 8
#define TN 8
// ACT: 0 = bias only
//      1 = fourier(bias+acc)  (even col -> sin, odd -> cos)
//      2 = cat: store raw at col n, fourier at col N+n (ldc = 2N)
//      3 = score: bias[n] - 2*acc   (bias = e2)
template <int ACT>
__global__ __launch_bounds__(256, 2)
void gemm_tn_kernel(const float* __restrict__ A, const float* __restrict__ B,
                    const float* __restrict__ bias, float* __restrict__ C,
                    int M, int N, int K, int ldc)
{
    __shared__ float As[BK][BM];
    __shared__ float Bs[BK][BN];

    const int tid = threadIdx.x;
    const int tx = tid & 15;          // 16 cols of threads
    const int ty = tid >> 4;          // 16 rows of threads

    const int m0 = blockIdx.y * BM;
    const int n0 = blockIdx.x * BN;

    const float* Ag = A + (size_t)m0 * K;
    const float* Bg = B + (size_t)n0 * K;

    const int lr = tid >> 1;          // 0..127  (row within tile)
    const int lc = (tid & 1) * 4;     // 0 or 4  (k offset, float4)

    float acc[TM][TN];
#pragma unroll
    for (int i = 0; i < TM; i++)
#pragma unroll
        for (int j = 0; j < TN; j++) acc[i][j] = 0.f;

    for (int k0 = 0; k0 < K; k0 += BK) {
        float4 av = *(const float4*)(Ag + (size_t)lr * K + k0 + lc);
        float4 bv = *(const float4*)(Bg + (size_t)lr * K + k0 + lc);
        __syncthreads();   // previous iteration's smem reads done
        As[lc + 0][lr] = av.x; As[lc + 1][lr] = av.y;
        As[lc + 2][lr] = av.z; As[lc + 3][lr] = av.w;
        Bs[lc + 0][lr] = bv.x; Bs[lc + 1][lr] = bv.y;
        Bs[lc + 2][lr] = bv.z; Bs[lc + 3][lr] = bv.w;
        __syncthreads();

#pragma unroll
        for (int kk = 0; kk < BK; kk++) {
            float4 a0 = *(const float4*)&As[kk][ty * TM];
            float4 a1 = *(const float4*)&As[kk][ty * TM + 4];
            float4 b0 = *(const float4*)&Bs[kk][tx * TN];
            float4 b1 = *(const float4*)&Bs[kk][tx * TN + 4];
            float af[TM] = {a0.x, a0.y, a0.z, a0.w, a1.x, a1.y, a1.z, a1.w};
            float bf[TN] = {b0.x, b0.y, b0.z, b0.w, b1.x, b1.y, b1.z, b1.w};
#pragma unroll
            for (int i = 0; i < TM; i++)
#pragma unroll
                for (int j = 0; j < TN; j++)
                    acc[i][j] = fmaf(af[i], bf[j], acc[i][j]);
        }
    }

    // epilogue
#pragma unroll
    for (int i = 0; i < TM; i++) {
        const int m = m0 + ty * TM + i;
        float* crow = C + (size_t)m * ldc;
#pragma unroll
        for (int j = 0; j < TN; j++) {
            const int n = n0 + tx * TN + j;
            const float s = acc[i][j];
            if (ACT == 0) {
                crow[n] = s + bias[n];
            } else if (ACT == 1) {
                const float v = s + bias[n];
                crow[n] = (n & 1) ? cosf(v) : sinf(v);
            } else if (ACT == 2) {
                const float v = s + bias[n];
                crow[n] = v;
                crow[N + n] = (n & 1) ? cosf(v) : sinf(v);
            } else { // 3: score
                crow[n] = bias[n] - 2.0f * s;
            }
        }
    }
}

// ---------------- e2[k] = ||emb[k]||^2 ----------------
__global__ void e2_kernel(const float* __restrict__ emb, float* __restrict__ e2)
{
    __shared__ float red[256];
    const int k = blockIdx.x;
    const float* row = emb + (size_t)k * DD;
    float s = 0.f;
    for (int d = threadIdx.x; d < DD; d += 256) { float v = row[d]; s += v * v; }
    red[threadIdx.x] = s;
    __syncthreads();
    for (int o = 128; o > 0; o >>= 1) {
        if (threadIdx.x < o) red[threadIdx.x] += red[threadIdx.x + o];
        __syncthreads();
    }
    if (threadIdx.x == 0) e2[k] = red[0];
}

// ---------------- per-row argmin over K scores (first-index tie-break) -------
__global__ void argmin_kernel(const float* __restrict__ scores, int* __restrict__ idx)
{
    __shared__ float bv[256];
    __shared__ int   bi[256];
    const int n = blockIdx.x;
    const float* row = scores + (size_t)n * KK;
    float best = 3.4e38f;
    int besti = 0;
    for (int k = threadIdx.x; k < KK; k += 256) {
        float v = row[k];
        if (v < best) { best = v; besti = k; }   // ascending scan keeps first
    }
    bv[threadIdx.x] = best;
    bi[threadIdx.x] = besti;
    __syncthreads();
    for (int o = 128; o > 0; o >>= 1) {
        if (threadIdx.x < o) {
            float vo = bv[threadIdx.x + o];
            int   io = bi[threadIdx.x + o];
            if (vo < bv[threadIdx.x] ||
                (vo == bv[threadIdx.x] && io < bi[threadIdx.x])) {
                bv[threadIdx.x] = vo; bi[threadIdx.x] = io;
            }
        }
        __syncthreads();
    }
    if (threadIdx.x == 0) idx[n] = bi[0];
}

// ---------------- mueller hash (numpy int64 wraparound semantics) ------------
__device__ __forceinline__ long long mueller_hash(long long x)
{
    const unsigned long long C = 73244475ull;
    x = (long long)((unsigned long long)((x >> 16) ^ x) * C);
    x = (long long)((unsigned long long)((x >> 16) ^ x) * C);
    return (x >> 16) ^ x;
}

// ---------------- quantize: out[n] = sum_{i=1..3} emb[hash(idx+i*K)&(K-1)]/3 --
__global__ void quant_kernel(const float* __restrict__ emb,
                             const int* __restrict__ idx,
                             float* __restrict__ out)
{
    const int n = blockIdx.x;
    const long long id = (long long)idx[n];
    int s0 = (int)(mueller_hash(id + 1LL * KK) & (long long)(KK - 1));
    int s1 = (int)(mueller_hash(id + 2LL * KK) & (long long)(KK - 1));
    int s2 = (int)(mueller_hash(id + 3LL * KK) & (long long)(KK - 1));
    const float4* e0 = (const float4*)(emb + (size_t)s0 * DD);
    const float4* e1 = (const float4*)(emb + (size_t)s1 * DD);
    const float4* e2p = (const float4*)(emb + (size_t)s2 * DD);
    float4* o = (float4*)(out + (size_t)n * DD);
    const int d = threadIdx.x;  // 256 threads * float4 = 1024 floats
    float4 a = e0[d], b = e1[d], c = e2p[d];
    float4 r;
    r.x = (a.x / 3.0f + b.x / 3.0f) + c.x / 3.0f;
    r.y = (a.y / 3.0f + b.y / 3.0f) + c.y / 3.0f;
    r.z = (a.z / 3.0f + b.z / 3.0f) + c.z / 3.0f;
    r.w = (a.w / 3.0f + b.w / 3.0f) + c.w / 3.0f;
    o[d] = r;
}

// ---------------- host launcher ----------------
extern "C" void kernel_launch(void* const* d_in, const int* in_sizes, int n_in,
                              void* d_out, int out_size)
{
    const float* x   = (const float*)d_in[0];   // [8192,1024]
    const float* w1  = (const float*)d_in[1];   // [4096,1024]
    const float* b1  = (const float*)d_in[2];   // [4096]
    const float* w2  = (const float*)d_in[3];   // [4096,8192]
    const float* b2  = (const float*)d_in[4];   // [4096]
    const float* w3  = (const float*)d_in[5];   // [4096,4096]
    const float* b3  = (const float*)d_in[6];   // [4096]
    const float* w4  = (const float*)d_in[7];   // [1024,4096]
    const float* b4  = (const float*)d_in[8];   // [1024]
    const float* emb = (const float*)d_in[9];   // [4096,1024]
    float* out = (float*)d_out;

    float *hcat, *h2, *h3, *z, *e2;
    int* idx;
    cudaGetSymbolAddress((void**)&hcat, g_hcat);
    cudaGetSymbolAddress((void**)&h2,   g_h2);
    cudaGetSymbolAddress((void**)&h3,   g_h3);
    cudaGetSymbolAddress((void**)&z,    g_z);
    cudaGetSymbolAddress((void**)&e2,   g_e2);
    cudaGetSymbolAddress((void**)&idx,  g_idx);

    // e2 = ||emb_k||^2
    e2_kernel<<<KK, 256>>>(emb, e2);

    // G1: hcat = [h1, fourier(h1)],  h1 = x @ w1.T + b1   -> [8192, 8192]
    {
        dim3 grid(HH / BN, NN / BM);
        gemm_tn_kernel<2><<<grid, 256>>>(x, w1, b1, hcat, NN, HH, DD, 2 * HH);
    }
    // G2: h2 = fourier(hcat @ w2.T + b2)  -> [8192, 4096]
    {
        dim3 grid(HH / BN, NN / BM);
        gemm_tn_kernel<1><<<grid, 256>>>(hcat, w2, b2, h2, NN, HH, 2 * HH, HH);
    }
    // G3: h3 = fourier(h2 @ w3.T + b3)
    {
        dim3 grid(HH / BN, NN / BM);
        gemm_tn_kernel<1><<<grid, 256>>>(h2, w3, b3, h3, NN, HH, HH, HH);
    }
    // G4: z = h3 @ w4.T + b4  -> [8192, 1024]
    {
        dim3 grid(DD / BN, NN / BM);
        gemm_tn_kernel<0><<<grid, 256>>>(h3, w4, b4, z, NN, DD, HH, DD);
    }
    // G5: scores = e2[k] - 2 * z @ emb.T   (reuse h2 buffer) -> [8192, 4096]
    {
        dim3 grid(KK / BN, NN / BM);
        gemm_tn_kernel<3><<<grid, 256>>>(z, emb, e2, h2, NN, KK, DD, KK);
    }
    // argmin per row
    argmin_kernel<<<NN, 256>>>(h2, idx);
    // hash + gather
    quant_kernel<<<NN, 256>>>(emb, idx, out);
}